// round 17
// baseline (speedup 1.0000x reference)
#include <cuda_runtime.h>
#include <cuda_fp16.h>
#include <cstdint>

#define EMB 128
#define NR 6
#define SA 272          // B smem row stride in bytes (136 fp16)
#define SH 136          // Sum_h row stride in halves (272B, conflict-free)
#define TILE 96         // edges per tile
#define THREADS 384     // 12 warps, monolithic phases, 2 CTAs/SM

// smem offsets (bytes)
#define OFF_A    0        // 96*256 swizzled   = 24576
#define OFF_B    24576    // 128*272           = 34816 -> 59392
#define OFF_SUM  59392    // 96*272 (fp16)     = 26112 -> 85504
#define OFF_RBFH 85504    // 96*48 (fp16 k16)  = 4608  -> 90112
#define OFF_WRH  90112    // 16*272 (fp16)     = 4352  -> 94464
#define OFF_IDX  94464    // 2 x 96*4          = 768   -> 95232
#define SMEM_TOT 95232    // (95232+1024r)*2 = 192512 <= 233472; ~40KB L1D left

// Precomputed table @ W_block projections in fp16: rows 0-95 Tsrc, 96-191 Tdst,
// 192-211 Tstep, 212-213 Teq (+bias folded into Teq rows). uint2 for 8B loads.
__device__ uint2 g_Th[214 * 32];

__device__ __forceinline__ uint32_t smem_u32(const void* p) {
    uint32_t a;
    asm("{ .reg .u64 t; cvta.to.shared.u64 t, %1; cvt.u32.u64 %0, t; }" : "=r"(a) : "l"(p));
    return a;
}
// silu(x) = 0.5x * (1 + tanh(x/2))  (fp32)
__device__ __forceinline__ float silu_f(float x) {
    float h = 0.5f * x, t;
    asm("tanh.approx.f32 %0, %1;" : "=f"(t) : "f"(h));
    return fmaf(h, t, h);
}
__device__ __forceinline__ uint32_t hadd2(uint32_t a, uint32_t b) {
    uint32_t r;
    asm("add.f16x2 %0, %1, %2;" : "=r"(r) : "r"(a), "r"(b));
    return r;
}
// packed fp16x2 silu: h = 0.5x; t = tanh(h); r = h*t + h
__device__ __forceinline__ uint32_t silu_h2(uint32_t x) {
    uint32_t h, t, r;
    asm("mul.f16x2 %0, %1, %2;" : "=r"(h) : "r"(x), "r"(0x38003800u));
    asm("tanh.approx.f16x2 %0, %1;" : "=r"(t) : "r"(h));
    asm("fma.rn.f16x2 %0, %1, %2, %1;" : "=r"(r) : "r"(h), "r"(t));
    return r;
}
__device__ __forceinline__ void ldsm4(uint32_t* r, uint32_t addr) {
    asm volatile("ldmatrix.sync.aligned.m8n8.x4.shared.b16 {%0,%1,%2,%3}, [%4];"
                 : "=r"(r[0]), "=r"(r[1]), "=r"(r[2]), "=r"(r[3]) : "r"(addr));
}
__device__ __forceinline__ void ldsm4t(uint32_t* r, uint32_t addr) {
    asm volatile("ldmatrix.sync.aligned.m8n8.x4.trans.shared.b16 {%0,%1,%2,%3}, [%4];"
                 : "=r"(r[0]), "=r"(r[1]), "=r"(r[2]), "=r"(r[3]) : "r"(addr));
}
__device__ __forceinline__ void mma_f16(float* d, const uint32_t* a, const uint32_t* b) {
    asm volatile("mma.sync.aligned.m16n8k16.row.col.f32.f16.f16.f32 "
                 "{%0,%1,%2,%3}, {%4,%5,%6,%7}, {%8,%9}, {%0,%1,%2,%3};"
                 : "+f"(d[0]), "+f"(d[1]), "+f"(d[2]), "+f"(d[3])
                 : "r"(a[0]), "r"(a[1]), "r"(a[2]), "r"(a[3]), "r"(b[0]), "r"(b[1]));
}

// ---------------------------------------------------------------------------
// Kernel 1: g_Th = fp16(tables @ W_blocks), blocked GEMM — W tile loaded ONCE
// per block into smem. 16 blocks = 4 groups x 4 col-chunks of 32 cols.
// ---------------------------------------------------------------------------
__global__ void precompute_kernel(const float* __restrict__ emb_table,
                                  const float* __restrict__ step_table,
                                  const float* __restrict__ equiv_table,
                                  const float* __restrict__ W,
                                  const float* __restrict__ b)
{
    __shared__ float Wb[EMB * 32];
    __shared__ float rows[8][EMB];
    const int g  = blockIdx.x >> 2;
    const int cc = blockIdx.x & 3;
    const int tid = threadIdx.x;

    const float* table; const float* Wsrc; int nr, rbase; bool addb = false;
    if (g == 0)      { table = emb_table;   Wsrc = W;                 nr = 96; rbase = 0;   }
    else if (g == 1) { table = emb_table;   Wsrc = W + EMB * EMB;     nr = 96; rbase = 96;  }
    else if (g == 2) { table = step_table;  Wsrc = W + 3 * EMB * EMB; nr = 20; rbase = 192; }
    else             { table = equiv_table; Wsrc = W + 4 * EMB * EMB; nr = 2;  rbase = 212; addb = true; }

    for (int i = tid; i < EMB * 32; i += 256) {
        int k = i >> 5, c = i & 31;
        Wb[i] = Wsrc[k * EMB + cc * 32 + c];
    }
    __syncthreads();

    const int c = tid & 31, rsub = tid >> 5;
    const float bias = addb ? b[cc * 32 + c] : 0.0f;
    for (int r0 = 0; r0 < nr; r0 += 8) {
        for (int i = tid; i < 8 * EMB; i += 256) {
            int rr = i >> 7, k = i & 127;
            if (r0 + rr < nr) rows[rr][k] = table[(r0 + rr) * EMB + k];
        }
        __syncthreads();
        const int r = r0 + rsub;
        if (r < nr) {
            float a0 = 0, a1 = 0, a2 = 0, a3 = 0;
            #pragma unroll
            for (int k = 0; k < EMB; k += 4) {
                a0 = fmaf(rows[rsub][k + 0], Wb[(k + 0) * 32 + c], a0);
                a1 = fmaf(rows[rsub][k + 1], Wb[(k + 1) * 32 + c], a1);
                a2 = fmaf(rows[rsub][k + 2], Wb[(k + 2) * 32 + c], a2);
                a3 = fmaf(rows[rsub][k + 3], Wb[(k + 3) * 32 + c], a3);
            }
            ((__half*)g_Th)[(rbase + r) * EMB + cc * 32 + c] =
                __float2half((a0 + a1) + (a2 + a3) + bias);
        }
        __syncthreads();
    }
}

// ---------------------------------------------------------------------------
// Kernel 2: persistent monolithic edge kernel, 2 CTAs/SM x 384 threads.
// Main GEMM: 12 warps 3(m)x4(n), 32x32 tiles, fp16 mma.sync.
// A-production on tensor core. 3 syncs/tile: [P0/P1] | [P2b,P2a] | [P3+P4].
// ---------------------------------------------------------------------------
__global__ __launch_bounds__(THREADS, 2)
void edge_kernel(const int* __restrict__ Z, const int* __restrict__ stepA,
                 const int* __restrict__ src, const int* __restrict__ dst,
                 const int* __restrict__ equiv,
                 const float* __restrict__ rbf, const float* __restrict__ dvec,
                 const float* __restrict__ W_rbf, const float* __restrict__ b_rbf,
                 const float* __restrict__ W2,
                 float* __restrict__ out, int E, int tiles)
{
    extern __shared__ char sm[];
    char*   const Asm  = sm + OFF_A;
    char*   const Bsm  = sm + OFF_B;
    __half* const Sumh = (__half*)(sm + OFF_SUM);
    char*   const RBFh = sm + OFF_RBFH;             // [96][48B] (k0..15 fp16 + pad)
    char*   const WRh  = sm + OFF_WRH;              // [16][272B]
    int*    const sidxA = (int*)(sm + OFF_IDX);     // [96]: Z[src] | step<<7
    int*    const sidxB = sidxA + TILE;             // [96]: Z[dst] | equiv<<7

    const int tid  = threadIdx.x;
    const int wid  = tid >> 5;
    const int lane = tid & 31;
    const int pe = tid % TILE;
    const int pq = tid / TILE;    // 0..3 role
    const int stride = gridDim.x;

    // ---- initial prefetch for first tile ----
    int   pfi = 0, pfi2 = 0;
    float pf0 = 1.0f, pf1 = 0, pf2 = 0, pf3 = 0, pf4 = 0, pf5 = 0;
    {
        const int t0 = blockIdx.x;
        const int gn = t0 * TILE + pe;
        const bool vn = (t0 < tiles) && (gn < E);
        if (pq == 0)      { if (vn) pfi = src[gn]; }
        else if (pq == 1) { if (vn) { pfi = dst[gn]; pfi2 = equiv[gn]; } }
        else if (pq == 2) {
            if (vn) {
                const float* rp = rbf + (size_t)gn * NR;
                float2 a = *(const float2*)(rp);
                float2 b = *(const float2*)(rp + 2);
                float2 c = *(const float2*)(rp + 4);
                pf0 = a.x; pf1 = a.y; pf2 = b.x; pf3 = b.y; pf4 = c.x; pf5 = c.y;
            }
        } else            { if (vn) pf0 = dvec[gn]; }
    }

    // ---- one-time: W2^T -> fp16 smem; W_rbf/bias -> fp16 smem [16][272B] ----
    for (int idx = tid; idx < EMB * EMB; idx += THREADS) {
        int k = idx >> 7, n = idx & 127;
        *(__half*)(Bsm + k * SA + n * 2) = __float2half(W2[idx]);
    }
    for (int i = tid; i < 16 * EMB; i += THREADS) {
        int k = i >> 7, n = i & 127;
        float v = (k < 6) ? W_rbf[k * EMB + n] : (k == 6 ? b_rbf[n] : 0.0f);
        *(__half*)(WRh + k * 272 + n * 2) = __float2half(v);
    }
    __syncthreads();

    const int wm = wid >> 2;      // 0..2  (m-group of 32 edges)  [main GEMM]
    const int wn = wid & 3;       // 0..3  (n-group of 32 cols)
    const int m0 = wm * 32;
    const uint32_t lmoff = (uint32_t)((lane & 15) * SA + (lane >> 4) * 16);
    const uint32_t A_u  = smem_u32(Asm);
    const uint32_t B_u  = smem_u32(Bsm);
    const uint32_t RH_u = smem_u32(RBFh);
    const uint32_t WR_u = smem_u32(WRh);
    // A swizzled read addressing (main GEMM): row = m0 + (lane&15)
    const uint32_t r3   = (uint32_t)(lane & 7);
    const uint32_t hxa  = (uint32_t)(((lane >> 4) ^ (lane & 1)) * 16);
    const uint32_t r6x  = (r3 & 6) * 16;
    const uint32_t AuBase = A_u + (uint32_t)(m0 + (lane & 15)) * 256 + hxa;
    // A-production GEMM: warp covers rows m0a..m0a+15, cols wn2*64..+63
    const int m0a = (wid >> 1) * 16;
    const int wn2 = wid & 1;
    const uint32_t RHfrag = RH_u + (uint32_t)((m0a + (lane & 15)) * 48 + (lane >> 4) * 16);
    const uint32_t WRfrag = WR_u + (uint32_t)((lane & 15) * 272 + (lane >> 4) * 16 + wn2 * 128);
    const int rowA = m0a + (lane >> 2);
    const int cbA  = wn2 * 128 + (lane & 3) * 4;   // byte col base in A row
    // preload Teq rows (fp16)
    const uint2 te0u = g_Th[212 * 32 + lane];
    const uint2 te1u = g_Th[213 * 32 + lane];
    float* const envo = out + (size_t)E * EMB;

    int prev_ebase = -1;

    for (int t = blockIdx.x; t < tiles; t += stride) {
        const int ebase = t * TILE;
        const int ge1 = ebase + pe;
        const bool v1 = (ge1 < E);

        // ---- P0/P1: copy-out(t-1) + stage(t) + prefetch(t+stride) ----
        if (prev_ebase >= 0) {
            #pragma unroll
            for (int i = 0; i < 8; i++) {
                const int r = wid * 8 + i;
                const int ge = prev_ebase + r;
                if (ge < E) {
                    uint2 u = *(uint2*)&Sumh[r * SH + lane * 4];
                    float2 a = __half22float2(*(__half2*)&u.x);
                    float2 b = __half22float2(*(__half2*)&u.y);
                    *(float4*)&out[(size_t)ge * EMB + lane * 4] = make_float4(a.x, a.y, b.x, b.y);
                }
            }
        }
        if (pq == 0) {
            int pk = 0;
            if (v1) { int s = pfi; pk = Z[s] | (stepA[s] << 7); }
            sidxA[pe] = pk;
        } else if (pq == 1) {
            int pk = 0;
            if (v1) { int dd = pfi; pk = Z[dd] | (pfi2 << 7); }
            sidxB[pe] = pk;
        } else if (pq == 2) {
            // stage rbf row as fp16 k0..5, k6=1.0 (bias slot), k7..15=0
            uint32_t p01, p23, p45;
            asm("cvt.rn.f16x2.f32 %0, %1, %2;" : "=r"(p01) : "f"(pf1), "f"(pf0));
            asm("cvt.rn.f16x2.f32 %0, %1, %2;" : "=r"(p23) : "f"(pf3), "f"(pf2));
            asm("cvt.rn.f16x2.f32 %0, %1, %2;" : "=r"(p45) : "f"(pf5), "f"(pf4));
            *(uint4*)(RBFh + pe * 48)      = make_uint4(p01, p23, p45, 0x00003C00u);
            *(uint4*)(RBFh + pe * 48 + 16) = make_uint4(0, 0, 0, 0);
        } else {
            if (v1) {
                float x = pf0 * 0.2f;
                float inv = 1.0f / x;
                float x2 = x * x;
                float x5 = x2 * x2 * x;
                float env = inv + x5 * (-28.0f + x * (48.0f + x * (-21.0f)));
                float coef = env * inv;
                const float PI = 3.14159265358979323846f;
                float th = PI * x;
                float s1 = __sinf(th), c1 = __cosf(th);
                float twoc = 2.0f * c1;
                float sp = 0.0f, s = s1;
                float o[NR];
                #pragma unroll
                for (int j = 0; j < NR; j++) {
                    o[j] = coef * s;
                    float sn = twoc * s - sp;
                    sp = s; s = sn;
                }
                float* op = envo + (size_t)ge1 * NR;
                *(float2*)(op + 0) = make_float2(o[0], o[1]);
                *(float2*)(op + 2) = make_float2(o[2], o[3]);
                *(float2*)(op + 4) = make_float2(o[4], o[5]);
            }
        }
        // prefetch tile t+stride
        {
            const int tn = t + stride;
            const int gn = tn * TILE + pe;
            const bool vn = (tn < tiles) && (gn < E);
            if (pq == 0)      { pfi = vn ? src[gn] : 0; }
            else if (pq == 1) { pfi = vn ? dst[gn] : 0; pfi2 = vn ? equiv[gn] : 0; }
            else if (pq == 2) {
                if (vn) {
                    const float* rp = rbf + (size_t)gn * NR;
                    float2 a = *(const float2*)(rp);
                    float2 b = *(const float2*)(rp + 2);
                    float2 c = *(const float2*)(rp + 4);
                    pf0 = a.x; pf1 = a.y; pf2 = b.x; pf3 = b.y; pf4 = c.x; pf5 = c.y;
                } else { pf0 = pf1 = pf2 = pf3 = pf4 = pf5 = 0.0f; }
            } else            { pf0 = vn ? dvec[gn] : 1.0f; }
        }
        __syncthreads();

        // ---- P2b: fp16 table gathers -> fp16 Sum (8 rows/warp); loads issue
        //      early and overlap the A-production MMAs below ----
        #pragma unroll
        for (int i = 0; i < 8; i++) {
            const int r = wid * 8 + i;
            const uint32_t pkA = (uint32_t)sidxA[r];
            const uint32_t pkB = (uint32_t)sidxB[r];
            const int zs = pkA & 127, st = pkA >> 7;
            const int zd = pkB & 127, eq = pkB >> 7;
            uint2 u0 = g_Th[zs * 32 + lane];
            uint2 u1 = g_Th[(96 + zd) * 32 + lane];
            uint2 u2 = g_Th[(192 + st) * 32 + lane];
            uint2 u3 = eq ? te1u : te0u;
            uint2 o;
            o.x = hadd2(hadd2(u0.x, u1.x), hadd2(u2.x, u3.x));
            o.y = hadd2(hadd2(u0.y, u1.y), hadd2(u2.y, u3.y));
            *(uint2*)&Sumh[r * SH + lane * 4] = o;
        }

        // ---- P2a: A = silu(rbf16 @ Wrbf16) via tensor core, store swizzled ----
        {
            uint32_t a[4];
            ldsm4(a, RHfrag);
            uint32_t b[16];
            ldsm4t(b + 0,  WRfrag);
            ldsm4t(b + 4,  WRfrag + 32);
            ldsm4t(b + 8,  WRfrag + 64);
            ldsm4t(b + 12, WRfrag + 96);
            float z[8][4];
            #pragma unroll
            for (int j = 0; j < 8; j++)
                z[j][0] = z[j][1] = z[j][2] = z[j][3] = 0.0f;
            #pragma unroll
            for (int j = 0; j < 8; j++)
                mma_f16(z[j], a, b + 2 * j);
            char* const ar1 = Asm + rowA * 256;
            char* const ar2 = ar1 + 8 * 256;
            const uint32_t x1 = (uint32_t)(rowA & 7) << 4;
            const uint32_t x2 = (uint32_t)((rowA + 8) & 7) << 4;
            #pragma unroll
            for (int j = 0; j < 8; j++) {
                const uint32_t byte = (uint32_t)(cbA + j * 16);
                const uint32_t ch = byte & 0xFFFFFFF0u, wi = byte & 15u;
                uint32_t u0, u1;
                float s0 = silu_f(z[j][0]), s1v = silu_f(z[j][1]);
                float s2 = silu_f(z[j][2]), s3 = silu_f(z[j][3]);
                asm("cvt.rn.f16x2.f32 %0, %1, %2;" : "=r"(u0) : "f"(s1v), "f"(s0));
                asm("cvt.rn.f16x2.f32 %0, %1, %2;" : "=r"(u1) : "f"(s3), "f"(s2));
                *(uint32_t*)(ar1 + ((ch ^ x1) | wi)) = u0;
                *(uint32_t*)(ar2 + ((ch ^ x2) | wi)) = u1;
            }
        }
        __syncthreads();

        // ---- P3: main GEMM 32x32 per warp, single-pass fp16, swizzled A ----
        float d[2][4][4];
        #pragma unroll
        for (int mt = 0; mt < 2; mt++)
            #pragma unroll
            for (int jj = 0; jj < 4; jj++)
                d[mt][jj][0] = d[mt][jj][1] = d[mt][jj][2] = d[mt][jj][3] = 0.0f;

        {
            const uint32_t Bu = B_u + wn * 64 + lmoff;
            #pragma unroll
            for (int ks = 0; ks < 8; ks++) {
                const uint32_t aoff = ((uint32_t)(ks * 32)) ^ r6x;
                uint32_t a[8];
                ldsm4(a + 0, AuBase + aoff);
                ldsm4(a + 4, AuBase + 4096 + aoff);
                uint32_t b[8];
                ldsm4t(b + 0, Bu + ks * 16 * SA);
                ldsm4t(b + 4, Bu + ks * 16 * SA + 32);
                #pragma unroll
                for (int mt = 0; mt < 2; mt++)
                    #pragma unroll
                    for (int jj = 0; jj < 4; jj++)
                        mma_f16(d[mt][jj], a + mt * 4, b + 2 * jj);
            }
        }

        // ---- P4 (fused, no barrier: Sumh inputs synced a phase ago; each
        //      warp RMWs only its own disjoint fragment region) ----
        #pragma unroll
        for (int mt = 0; mt < 2; mt++) {
            const int r1 = m0 + mt * 16 + (lane >> 2);
            __half* S1 = Sumh + r1 * SH;
            __half* S2 = Sumh + (r1 + 8) * SH;
            #pragma unroll
            for (int jj = 0; jj < 4; jj++) {
                const int c = wn * 32 + jj * 8 + (lane & 3) * 2;
                const float* dd = d[mt][jj];
                uint32_t dh0, dh1;
                asm("cvt.rn.f16x2.f32 %0, %1, %2;" : "=r"(dh0) : "f"(dd[1]), "f"(dd[0]));
                asm("cvt.rn.f16x2.f32 %0, %1, %2;" : "=r"(dh1) : "f"(dd[3]), "f"(dd[2]));
                uint32_t* p1 = (uint32_t*)&S1[c];
                uint32_t* p2 = (uint32_t*)&S2[c];
                *p1 = silu_h2(hadd2(*p1, dh0));
                *p2 = silu_h2(hadd2(*p2, dh1));
            }
        }
        __syncthreads();

        prev_ebase = ebase;
    }

    // ---- final copy-out ----
    if (prev_ebase >= 0) {
        #pragma unroll
        for (int i = 0; i < 8; i++) {
            const int r = wid * 8 + i;
            const int ge = prev_ebase + r;
            if (ge < E) {
                uint2 u = *(uint2*)&Sumh[r * SH + lane * 4];
                float2 a = __half22float2(*(__half2*)&u.x);
                float2 b = __half22float2(*(__half2*)&u.y);
                *(float4*)&out[(size_t)ge * EMB + lane * 4] = make_float4(a.x, a.y, b.x, b.y);
            }
        }
    }
}

// ---------------------------------------------------------------------------
extern "C" void kernel_launch(void* const* d_in, const int* in_sizes, int n_in,
                              void* d_out, int out_size)
{
    const int*   Z          = (const int*)d_in[0];
    const int*   stepA      = (const int*)d_in[1];
    const int*   src        = (const int*)d_in[2];
    const int*   dst        = (const int*)d_in[3];
    const int*   equiv      = (const int*)d_in[4];
    const float* rbf        = (const float*)d_in[5];
    const float* dvec       = (const float*)d_in[6];
    const float* emb_table  = (const float*)d_in[7];
    const float* step_table = (const float*)d_in[8];
    const float* equiv_tab  = (const float*)d_in[9];
    const float* W_rbf      = (const float*)d_in[10];
    const float* b_rbf      = (const float*)d_in[11];
    const float* W          = (const float*)d_in[12];
    const float* b          = (const float*)d_in[13];
    float* out = (float*)d_out;

    const int E = in_sizes[2];
    const int tiles = (E + TILE - 1) / TILE;

    static int sms = 0;
    if (sms == 0) {
        if (cudaDeviceGetAttribute(&sms, cudaDevAttrMultiProcessorCount, 0) != cudaSuccess || sms <= 0)
            sms = 148;
    }
    int grid = 2 * sms;
    if (grid > tiles) grid = tiles;

    cudaFuncSetAttribute(edge_kernel, cudaFuncAttributeMaxDynamicSharedMemorySize, SMEM_TOT);

    precompute_kernel<<<16, 256>>>(emb_table, step_table, equiv_tab, W, b);
    edge_kernel<<<grid, THREADS, SMEM_TOT>>>(Z, stepA, src, dst, equiv,
                                             rbf, dvec, W_rbf, b_rbf,
                                             W + 2 * EMB * EMB, out, E, tiles);
}